// round 13
// baseline (speedup 1.0000x reference)
#include <cuda_runtime.h>
#include <cuda_fp16.h>
#include <cstdint>

#define NU 200000
#define NI 100000
#define DIM 64
#define NE 3200000
#define CAPU 64          // max user degree (mean 16, sigma 4)
#define CAPI 128         // max item degree (mean 32, sigma 5.7)
#define UFB (NU / 64)    // 3125 fused blocks, u side
#define IFB ((NI + 63) / 64)  // 1563 (last block has 32 pad rows)

// ---------------- scratch (static __device__, no allocation) ----------------
__device__ int  g_u_cnt[NU];
__device__ int  g_i_cnt[NI];
__device__ __align__(16) int2 g_bkt_u[(size_t)NU * CAPU];
__device__ __align__(16) int2 g_bkt_i[(size_t)NI * CAPI];
__device__ __align__(16) float   g_hu[(size_t)NU * DIM];
__device__ __align__(16) float   g_hi[(size_t)NI * DIM];
// fp16 gather tables (row = 32 half2 = 128B)
__device__ __align__(16) __half2 g_ue16[(size_t)NU * 32];
__device__ __align__(16) __half2 g_ie16[(size_t)NI * 32];
__device__ __align__(16) __half2 g_hu16[(size_t)NU * 32];
__device__ __align__(16) __half2 g_hi16[(size_t)NI * 32];

// ---------------- init: zero degree counters + fp16 table convert ----------------
__global__ void init_kernel(const float* __restrict__ ue, const float* __restrict__ ie,
                            __half2* __restrict__ ue16, __half2* __restrict__ ie16,
                            int* __restrict__ u_cnt, int* __restrict__ i_cnt) {
    int t = blockIdx.x * 256 + threadIdx.x;
    int N = gridDim.x * 256;
    for (int j = t; j < NU; j += N) u_cnt[j] = 0;
    for (int j = t; j < NI; j += N) i_cnt[j] = 0;
    const float2* ue2 = (const float2*)ue;
    for (int j = t; j < NU * 32; j += N) {
        float2 x = ue2[j];
        ue16[j] = __floats2half2_rn(x.x, x.y);
    }
    const float2* ie2 = (const float2*)ie;
    for (int j = t; j < NI * 32; j += N) {
        float2 x = ie2[j];
        ie16[j] = __floats2half2_rn(x.x, x.y);
    }
}

// ---------------- scatter into fixed-capacity buckets (counts come for free) ----------------
__global__ void scatter_kernel(const int* __restrict__ u_idx, const int* __restrict__ i_idx,
                               const float* __restrict__ w_u2i, const float* __restrict__ w_i2u,
                               int* __restrict__ u_cnt, int* __restrict__ i_cnt,
                               int2* __restrict__ bkt_u, int2* __restrict__ bkt_i) {
    int e = blockIdx.x * 256 + threadIdx.x;
    if (e >= NE) return;
    int u = u_idx[e];
    int it = i_idx[e];
    int pu = atomicAdd(&u_cnt[u], 1);
    bkt_u[(size_t)u * CAPU + pu] = make_int2(it, __float_as_int(w_u2i[e]));
    int pi = atomicAdd(&i_cnt[it], 1);
    bkt_i[(size_t)it * CAPI + pi] = make_int2(u, __float_as_int(w_i2u[e]));
}

// ---------------- fused layer: gather -> smem x -> mma gemm -> relu/L2 -> store ----------------
__device__ __forceinline__ void accum8(float* acc, float4 r, float w) {
    __half2* h = (__half2*)&r;
#pragma unroll
    for (int p = 0; p < 4; p++) {
        float2 f = __half22float2(h[p]);
        acc[2 * p]     += w * f.x;
        acc[2 * p + 1] += w * f.y;
    }
}

__device__ __forceinline__ void split2(float2 v, __half2& hi, __half2& lo) {
    hi = __floats2half2_rn(v.x, v.y);
    float2 b = __half22float2(hi);
    lo = __floats2half2_rn(v.x - b.x, v.y - b.y);
}

#define MMA16816(c, a0, a1, a2, a3, b0, b1)                                   \
    asm volatile("mma.sync.aligned.m16n8k16.row.col.f32.f16.f16.f32 "         \
                 "{%0,%1,%2,%3}, {%4,%5,%6,%7}, {%8,%9}, {%0,%1,%2,%3};"      \
                 : "+f"(c[0]), "+f"(c[1]), "+f"(c[2]), "+f"(c[3])             \
                 : "r"(a0), "r"(a1), "r"(a2), "r"(a3), "r"(b0), "r"(b1))

// dynamic smem layout (halves): Whi[64*136], Wlo, Xhi[64*136], Xlo  = 69632 B
#define SM_W  (64 * 136)
#define SMEMB (4 * SM_W * 2)

__global__ void __launch_bounds__(256, 3) fused_kernel(
    const float* __restrict__ hu_self, const float* __restrict__ hi_self,
    const __half2* __restrict__ tab_u,   // gather table for u rows (= item side)
    const __half2* __restrict__ tab_i,   // gather table for i rows (= user side)
    const int* __restrict__ cnt_u, const int* __restrict__ cnt_i,
    const int2* __restrict__ bkt_u, const int2* __restrict__ bkt_i,
    const float* __restrict__ Wu_l, const float* __restrict__ Wi_l,
    float* __restrict__ out_u, float* __restrict__ out_i,
    __half2* __restrict__ o16_u, __half2* __restrict__ o16_i)
{
    extern __shared__ __half sm[];
    __half* Whi = sm;
    __half* Wlo = sm + SM_W;
    __half* Xhi = sm + 2 * SM_W;
    __half* Xlo = sm + 3 * SM_W;

    bool isU = blockIdx.x < UFB;
    int blk = isU ? blockIdx.x : blockIdx.x - UFB;
    int R = isU ? NU : NI;
    int base = blk * 64;
    const float* W = isU ? Wu_l : Wi_l;
    const float* hsrc = isU ? hu_self : hi_self;
    const float4* gt = (const float4*)(isU ? tab_u : tab_i);
    const int2* bkt = isU ? bkt_u : bkt_i;
    const int* cnt = isU ? cnt_u : cnt_i;
    size_t cap = isU ? CAPU : CAPI;

    // ---- fill W tiles (split fp16) ----
    for (int t = threadIdx.x; t < 64 * 128; t += 256) {
        int n = t >> 7, k = t & 127;
        float w = W[t];
        __half h = __float2half_rn(w);
        Whi[n * 136 + k] = h;
        Wlo[n * 136 + k] = __float2half_rn(w - __half2float(h));
    }

    int warp = threadIdx.x >> 5;
    int lane = threadIdx.x & 31;
    int q = lane >> 3;
    int m = lane & 7;

    // ---- gather phase: warp w handles rows base + w*8 .. +7 ----
#pragma unroll 1
    for (int r = 0; r < 8; r++) {
        int rloc = warp * 8 + r;
        int row = base + rloc;
        bool valid = row < R;
        int rowc = valid ? row : R - 1;
        int deg = valid ? cnt[rowc] : 0;
        size_t bb = (size_t)rowc * cap;

        float2 hs = ((const float2*)hsrc)[(size_t)rowc * 32 + lane];

        float acc[8];
#pragma unroll
        for (int j = 0; j < 8; j++) acc[j] = 0.f;

        int e = 0;
        for (; e + 8 <= deg; e += 8) {
            int2 E0 = __ldcs(bkt + bb + e + q);
            int2 E1 = __ldcs(bkt + bb + e + 4 + q);
            float4 r0 = gt[(size_t)E0.x * 8 + m];
            float4 r1 = gt[(size_t)E1.x * 8 + m];
            accum8(acc, r0, __int_as_float(E0.y));
            accum8(acc, r1, __int_as_float(E1.y));
        }
        for (; e < deg; e += 4) {
            int idx = e + q;
            int ci = (idx < deg) ? idx : (deg - 1);
            int2 E = __ldcs(bkt + bb + ci);
            float w = (idx < deg) ? __int_as_float(E.y) : 0.f;
            float4 rr = gt[(size_t)E.x * 8 + m];
            accum8(acc, rr, w);
        }
        // reduce across the 4 lane-groups (every lane ends with its m-group totals)
#pragma unroll
        for (int j = 0; j < 8; j++) {
            acc[j] += __shfl_xor_sync(0xffffffffu, acc[j], 8);
            acc[j] += __shfl_xor_sync(0xffffffffu, acc[j], 16);
        }

        // stage split-fp16 x into smem: self half at k=2*lane, neigh half at k=64+m*8..
        __half2 shi, slo;
        split2(hs, shi, slo);
        *(__half2*)&Xhi[rloc * 136 + 2 * lane] = shi;
        *(__half2*)&Xlo[rloc * 136 + 2 * lane] = slo;
        if (q == 0) {
#pragma unroll
            for (int jp = 0; jp < 4; jp++) {
                __half2 nh, nl;
                split2(make_float2(acc[2 * jp], acc[2 * jp + 1]), nh, nl);
                *(__half2*)&Xhi[rloc * 136 + 64 + m * 8 + 2 * jp] = nh;
                *(__half2*)&Xlo[rloc * 136 + 64 + m * 8 + 2 * jp] = nl;
            }
        }
    }
    __syncthreads();

    // ---- gemm phase: warps 0-3, each 16 rows x all 64 outputs ----
    if (warp >= 4) return;
    int gr = lane >> 2;      // 0..7
    int tq = lane & 3;       // 0..3
    int row0l = warp * 16;

    float acc[8][4];
#pragma unroll
    for (int t = 0; t < 8; t++)
#pragma unroll
        for (int j = 0; j < 4; j++) acc[t][j] = 0.f;

#pragma unroll
    for (int s = 0; s < 8; s++) {
        int ka = s * 16 + tq * 2;
        uint32_t ah0 = *(uint32_t*)&Xhi[(row0l + gr) * 136 + ka];
        uint32_t ah1 = *(uint32_t*)&Xhi[(row0l + gr + 8) * 136 + ka];
        uint32_t ah2 = *(uint32_t*)&Xhi[(row0l + gr) * 136 + ka + 8];
        uint32_t ah3 = *(uint32_t*)&Xhi[(row0l + gr + 8) * 136 + ka + 8];
        uint32_t al0 = *(uint32_t*)&Xlo[(row0l + gr) * 136 + ka];
        uint32_t al1 = *(uint32_t*)&Xlo[(row0l + gr + 8) * 136 + ka];
        uint32_t al2 = *(uint32_t*)&Xlo[(row0l + gr) * 136 + ka + 8];
        uint32_t al3 = *(uint32_t*)&Xlo[(row0l + gr + 8) * 136 + ka + 8];
#pragma unroll
        for (int t = 0; t < 8; t++) {
            int n = t * 8 + gr;
            uint32_t bh0 = *(uint32_t*)&Whi[n * 136 + ka];
            uint32_t bh1 = *(uint32_t*)&Whi[n * 136 + ka + 8];
            uint32_t bl0 = *(uint32_t*)&Wlo[n * 136 + ka];
            uint32_t bl1 = *(uint32_t*)&Wlo[n * 136 + ka + 8];
            MMA16816(acc[t], ah0, ah1, ah2, ah3, bh0, bh1);   // Whi * xhi
            MMA16816(acc[t], al0, al1, al2, al3, bh0, bh1);   // Whi * xlo
            MMA16816(acc[t], ah0, ah1, ah2, ah3, bl0, bl1);   // Wlo * xhi
        }
    }

    // ---- epilogue: ReLU + row L2 norm + store (fp32 + fp16 gather copy) ----
    float ss0 = 0.f, ss1 = 0.f;
#pragma unroll
    for (int t = 0; t < 8; t++) {
        acc[t][0] = fmaxf(acc[t][0], 0.f);
        acc[t][1] = fmaxf(acc[t][1], 0.f);
        acc[t][2] = fmaxf(acc[t][2], 0.f);
        acc[t][3] = fmaxf(acc[t][3], 0.f);
        ss0 += acc[t][0] * acc[t][0] + acc[t][1] * acc[t][1];
        ss1 += acc[t][2] * acc[t][2] + acc[t][3] * acc[t][3];
    }
    ss0 += __shfl_xor_sync(0xffffffffu, ss0, 1);
    ss0 += __shfl_xor_sync(0xffffffffu, ss0, 2);
    ss1 += __shfl_xor_sync(0xffffffffu, ss1, 1);
    ss1 += __shfl_xor_sync(0xffffffffu, ss1, 2);
    float inv0 = 1.0f / fmaxf(sqrtf(ss0), 1e-12f);
    float inv1 = 1.0f / fmaxf(sqrtf(ss1), 1e-12f);

    float* out = isU ? out_u : out_i;
    __half2* out16 = isU ? o16_u : o16_i;
    int r0 = base + row0l + gr, r1 = base + row0l + gr + 8;
    float2* o2 = (float2*)out;
    if (r0 < R) {
#pragma unroll
        for (int t = 0; t < 8; t++) {
            float y0 = acc[t][0] * inv0, y1 = acc[t][1] * inv0;
            o2[(size_t)r0 * 32 + t * 4 + tq] = make_float2(y0, y1);
            out16[(size_t)r0 * 32 + t * 4 + tq] = __floats2half2_rn(y0, y1);
        }
    }
    if (r1 < R) {
#pragma unroll
        for (int t = 0; t < 8; t++) {
            float y0 = acc[t][2] * inv1, y1 = acc[t][3] * inv1;
            o2[(size_t)r1 * 32 + t * 4 + tq] = make_float2(y0, y1);
            out16[(size_t)r1 * 32 + t * 4 + tq] = __floats2half2_rn(y0, y1);
        }
    }
}

// ---------------- launch ----------------
extern "C" void kernel_launch(void* const* d_in, const int* in_sizes, int n_in,
                              void* d_out, int out_size) {
    const float* user_emb = (const float*)d_in[0];
    const float* item_emb = (const float*)d_in[1];
    const float* Wu       = (const float*)d_in[2];   // [2,64,128]
    const float* Wi       = (const float*)d_in[3];
    const int*   u_idx    = (const int*)d_in[4];
    const int*   i_idx    = (const int*)d_in[5];
    const float* w_u2i    = (const float*)d_in[6];
    const float* w_i2u    = (const float*)d_in[7];
    float* out = (float*)d_out;

    void* p;
    int *u_cnt, *i_cnt;
    int2 *bkt_u, *bkt_i;
    float *hu, *hi;
    __half2 *ue16, *ie16, *hu16, *hi16;
    cudaGetSymbolAddress(&p, g_u_cnt);  u_cnt  = (int*)p;
    cudaGetSymbolAddress(&p, g_i_cnt);  i_cnt  = (int*)p;
    cudaGetSymbolAddress(&p, g_bkt_u);  bkt_u  = (int2*)p;
    cudaGetSymbolAddress(&p, g_bkt_i);  bkt_i  = (int2*)p;
    cudaGetSymbolAddress(&p, g_hu);     hu     = (float*)p;
    cudaGetSymbolAddress(&p, g_hi);     hi     = (float*)p;
    cudaGetSymbolAddress(&p, g_ue16);   ue16   = (__half2*)p;
    cudaGetSymbolAddress(&p, g_ie16);   ie16   = (__half2*)p;
    cudaGetSymbolAddress(&p, g_hu16);   hu16   = (__half2*)p;
    cudaGetSymbolAddress(&p, g_hi16);   hi16   = (__half2*)p;

    static int attr_done = 0;
    if (!attr_done) {
        cudaFuncSetAttribute(fused_kernel, cudaFuncAttributeMaxDynamicSharedMemorySize, SMEMB);
        attr_done = 1;
    }

    const int EB = (NE + 255) / 256;     // 12500

    // CSR build: init + scatter only
    init_kernel<<<1216, 256>>>(user_emb, item_emb, ue16, ie16, u_cnt, i_cnt);
    scatter_kernel<<<EB, 256>>>(u_idx, i_idx, w_u2i, w_i2u,
                                u_cnt, i_cnt, bkt_u, bkt_i);

    // layer 0: fused gather+gemm, merged u+i grid
    fused_kernel<<<UFB + IFB, 256, SMEMB>>>(user_emb, item_emb, ie16, ue16,
                                            u_cnt, i_cnt, bkt_u, bkt_i,
                                            Wu, Wi, hu, hi, hu16, hi16);
    // layer 1 (final fp16 copies go to dead scratch tables)
    fused_kernel<<<UFB + IFB, 256, SMEMB>>>(hu, hi, hi16, hu16,
                                            u_cnt, i_cnt, bkt_u, bkt_i,
                                            Wu + 64 * 128, Wi + 64 * 128,
                                            out, out + (size_t)NU * DIM, ue16, ie16);
}

// round 14
// speedup vs baseline: 1.2638x; 1.2638x over previous
#include <cuda_runtime.h>
#include <cuda_fp16.h>
#include <cstdint>

#define NU 200000
#define NI 100000
#define DIM 64
#define NE 3200000
#define CAPU 64          // max user degree (mean 16, sigma 4)
#define CAPI 128         // max item degree (mean 32, sigma 5.7)
#define UFB (NU / 64)    // 3125 fused blocks, u side
#define IFB ((NI + 63) / 64)  // 1563 (last block has 32 pad rows)

// ---------------- scratch (static __device__, no allocation) ----------------
__device__ int  g_u_cnt[NU];
__device__ int  g_i_cnt[NI];
__device__ __align__(16) int2 g_bkt_u[(size_t)NU * CAPU];
__device__ __align__(16) int2 g_bkt_i[(size_t)NI * CAPI];
// fp16 tables (row = 32 half2 = 128B): inputs and layer-0 outputs
__device__ __align__(16) __half2 g_ue16[(size_t)NU * 32];
__device__ __align__(16) __half2 g_ie16[(size_t)NI * 32];
__device__ __align__(16) __half2 g_hu16[(size_t)NU * 32];
__device__ __align__(16) __half2 g_hi16[(size_t)NI * 32];

// ---------------- init: zero degree counters + fp16 table convert ----------------
__global__ void init_kernel(const float* __restrict__ ue, const float* __restrict__ ie,
                            __half2* __restrict__ ue16, __half2* __restrict__ ie16,
                            int* __restrict__ u_cnt, int* __restrict__ i_cnt) {
    int t = blockIdx.x * 256 + threadIdx.x;
    int N = gridDim.x * 256;
    for (int j = t; j < NU; j += N) u_cnt[j] = 0;
    for (int j = t; j < NI; j += N) i_cnt[j] = 0;
    const float2* ue2 = (const float2*)ue;
    for (int j = t; j < NU * 32; j += N) {
        float2 x = ue2[j];
        ue16[j] = __floats2half2_rn(x.x, x.y);
    }
    const float2* ie2 = (const float2*)ie;
    for (int j = t; j < NI * 32; j += N) {
        float2 x = ie2[j];
        ie16[j] = __floats2half2_rn(x.x, x.y);
    }
}

// ---------------- scatter into fixed-capacity buckets (2 edges/thread) ----------------
__global__ void scatter_kernel(const int* __restrict__ u_idx, const int* __restrict__ i_idx,
                               const float* __restrict__ w_u2i, const float* __restrict__ w_i2u,
                               int* __restrict__ u_cnt, int* __restrict__ i_cnt,
                               int2* __restrict__ bkt_u, int2* __restrict__ bkt_i) {
    int e = (blockIdx.x * 256 + threadIdx.x) * 2;
    if (e + 2 > NE) return;
    int2 u2 = *(const int2*)(u_idx + e);
    int2 i2 = *(const int2*)(i_idx + e);
    float2 wu = *(const float2*)(w_u2i + e);
    float2 wi = *(const float2*)(w_i2u + e);
    int pu0 = atomicAdd(&u_cnt[u2.x], 1);
    int pu1 = atomicAdd(&u_cnt[u2.y], 1);
    bkt_u[(size_t)u2.x * CAPU + pu0] = make_int2(i2.x, __float_as_int(wu.x));
    bkt_u[(size_t)u2.y * CAPU + pu1] = make_int2(i2.y, __float_as_int(wu.y));
    int pi0 = atomicAdd(&i_cnt[i2.x], 1);
    int pi1 = atomicAdd(&i_cnt[i2.y], 1);
    bkt_i[(size_t)i2.x * CAPI + pi0] = make_int2(u2.x, __float_as_int(wi.x));
    bkt_i[(size_t)i2.y * CAPI + pi1] = make_int2(u2.y, __float_as_int(wi.y));
}

// ---------------- fused layer: fp16 gather -> smem x -> mma gemm -> relu/L2 -> store ----------------
#define MMA16816(c, a0, a1, a2, a3, b0, b1)                                   \
    asm volatile("mma.sync.aligned.m16n8k16.row.col.f32.f16.f16.f32 "         \
                 "{%0,%1,%2,%3}, {%4,%5,%6,%7}, {%8,%9}, {%0,%1,%2,%3};"      \
                 : "+f"(c[0]), "+f"(c[1]), "+f"(c[2]), "+f"(c[3])             \
                 : "r"(a0), "r"(a1), "r"(a2), "r"(a3), "r"(b0), "r"(b1))

__device__ __forceinline__ __half2 shfl_xor_h2(__half2 v, int m) {
    unsigned u = *(unsigned*)&v;
    u = __shfl_xor_sync(0xffffffffu, u, m);
    return *(__half2*)&u;
}

// dynamic smem (halves): Whi[64*136], Wlo[64*136], Xhi[64*136] = 52224 B
#define SM_W  (64 * 136)
#define SMEMB (3 * SM_W * 2)

__global__ void __launch_bounds__(256, 4) fused_kernel(
    const __half2* __restrict__ self_u, const __half2* __restrict__ self_i,
    const __half2* __restrict__ tab_u,   // gather table for u rows (= item side)
    const __half2* __restrict__ tab_i,   // gather table for i rows (= user side)
    const int* __restrict__ cnt_u, const int* __restrict__ cnt_i,
    const int2* __restrict__ bkt_u, const int2* __restrict__ bkt_i,
    const float* __restrict__ Wu_l, const float* __restrict__ Wi_l,
    float* __restrict__ out_u, float* __restrict__ out_i,
    __half2* __restrict__ o16_u, __half2* __restrict__ o16_i,
    int w32)   // 1: write fp32 outputs (final layer); 0: write fp16 tables (layer 0)
{
    extern __shared__ __half sm[];
    __half* Whi = sm;
    __half* Wlo = sm + SM_W;
    __half* Xhi = sm + 2 * SM_W;

    bool isU = blockIdx.x < UFB;
    int blk = isU ? blockIdx.x : blockIdx.x - UFB;
    int R = isU ? NU : NI;
    int base = blk * 64;
    const float* W = isU ? Wu_l : Wi_l;
    const __half2* hself = isU ? self_u : self_i;
    const float4* gt = (const float4*)(isU ? tab_u : tab_i);
    const int2* bkt = isU ? bkt_u : bkt_i;
    const int* cnt = isU ? cnt_u : cnt_i;
    size_t cap = isU ? CAPU : CAPI;

    // ---- fill W tiles (split fp16) ----
    for (int t = threadIdx.x; t < 64 * 128; t += 256) {
        int n = t >> 7, k = t & 127;
        float w = W[t];
        __half h = __float2half_rn(w);
        Whi[n * 136 + k] = h;
        Wlo[n * 136 + k] = __float2half_rn(w - __half2float(h));
    }

    int warp = threadIdx.x >> 5;
    int lane = threadIdx.x & 31;
    int q = lane >> 3;
    int m = lane & 7;

    // ---- gather phase: warp w handles rows base + w*8 .. +7 ----
#pragma unroll 1
    for (int r = 0; r < 8; r++) {
        int rloc = warp * 8 + r;
        int row = base + rloc;
        bool valid = row < R;
        int rowc = valid ? row : R - 1;
        int deg = valid ? cnt[rowc] : 0;
        size_t bb = (size_t)rowc * cap;

        // self half: copy fp16 row directly into smem
        __half2 hs = hself[(size_t)rowc * 32 + lane];
        *(__half2*)&Xhi[rloc * 136 + 2 * lane] = hs;

        __half2 a0[4], a1[4];
#pragma unroll
        for (int j = 0; j < 4; j++) {
            a0[j] = __floats2half2_rn(0.f, 0.f);
            a1[j] = __floats2half2_rn(0.f, 0.f);
        }

        int e = 0;
        for (; e + 8 <= deg; e += 8) {
            int2 E0 = __ldcs(bkt + bb + e + q);
            int2 E1 = __ldcs(bkt + bb + e + 4 + q);
            float4 r0 = gt[(size_t)E0.x * 8 + m];
            float4 r1 = gt[(size_t)E1.x * 8 + m];
            __half2 w0 = __half2half2(__float2half_rn(__int_as_float(E0.y)));
            __half2 w1 = __half2half2(__float2half_rn(__int_as_float(E1.y)));
            __half2* h0 = (__half2*)&r0;
            __half2* h1 = (__half2*)&r1;
#pragma unroll
            for (int j = 0; j < 4; j++) {
                a0[j] = __hfma2(h0[j], w0, a0[j]);
                a1[j] = __hfma2(h1[j], w1, a1[j]);
            }
        }
        for (; e < deg; e += 4) {
            int idx = e + q;
            int ci = (idx < deg) ? idx : (deg - 1);
            int2 E = __ldcs(bkt + bb + ci);
            float wf = (idx < deg) ? __int_as_float(E.y) : 0.f;
            float4 rr = gt[(size_t)E.x * 8 + m];
            __half2 w = __half2half2(__float2half_rn(wf));
            __half2* h = (__half2*)&rr;
#pragma unroll
            for (int j = 0; j < 4; j++) a0[j] = __hfma2(h[j], w, a0[j]);
        }

        // merge streams + reduce across the 4 lane-groups (packed fp16)
#pragma unroll
        for (int j = 0; j < 4; j++) {
            __half2 s = __hadd2(a0[j], a1[j]);
            s = __hadd2(s, shfl_xor_h2(s, 8));
            s = __hadd2(s, shfl_xor_h2(s, 16));
            a0[j] = s;
        }
        if (q == 0) {
#pragma unroll
            for (int j = 0; j < 4; j++)
                *(__half2*)&Xhi[rloc * 136 + 64 + m * 8 + 2 * j] = a0[j];
        }
    }
    __syncthreads();

    // ---- gemm phase: warps 0-3, each 16 rows x all 64 outputs ----
    if (warp >= 4) return;
    int gr = lane >> 2;      // 0..7
    int tq = lane & 3;       // 0..3
    int row0l = warp * 16;

    float acc[8][4];
#pragma unroll
    for (int t = 0; t < 8; t++)
#pragma unroll
        for (int j = 0; j < 4; j++) acc[t][j] = 0.f;

#pragma unroll
    for (int s = 0; s < 8; s++) {
        int ka = s * 16 + tq * 2;
        uint32_t ah0 = *(uint32_t*)&Xhi[(row0l + gr) * 136 + ka];
        uint32_t ah1 = *(uint32_t*)&Xhi[(row0l + gr + 8) * 136 + ka];
        uint32_t ah2 = *(uint32_t*)&Xhi[(row0l + gr) * 136 + ka + 8];
        uint32_t ah3 = *(uint32_t*)&Xhi[(row0l + gr + 8) * 136 + ka + 8];
#pragma unroll
        for (int t = 0; t < 8; t++) {
            int n = t * 8 + gr;
            uint32_t bh0 = *(uint32_t*)&Whi[n * 136 + ka];
            uint32_t bh1 = *(uint32_t*)&Whi[n * 136 + ka + 8];
            uint32_t bl0 = *(uint32_t*)&Wlo[n * 136 + ka];
            uint32_t bl1 = *(uint32_t*)&Wlo[n * 136 + ka + 8];
            MMA16816(acc[t], ah0, ah1, ah2, ah3, bh0, bh1);   // Whi * x
            MMA16816(acc[t], ah0, ah1, ah2, ah3, bl0, bl1);   // Wlo * x
        }
    }

    // ---- epilogue: ReLU + row L2 norm + store ----
    float ss0 = 0.f, ss1 = 0.f;
#pragma unroll
    for (int t = 0; t < 8; t++) {
        acc[t][0] = fmaxf(acc[t][0], 0.f);
        acc[t][1] = fmaxf(acc[t][1], 0.f);
        acc[t][2] = fmaxf(acc[t][2], 0.f);
        acc[t][3] = fmaxf(acc[t][3], 0.f);
        ss0 += acc[t][0] * acc[t][0] + acc[t][1] * acc[t][1];
        ss1 += acc[t][2] * acc[t][2] + acc[t][3] * acc[t][3];
    }
    ss0 += __shfl_xor_sync(0xffffffffu, ss0, 1);
    ss0 += __shfl_xor_sync(0xffffffffu, ss0, 2);
    ss1 += __shfl_xor_sync(0xffffffffu, ss1, 1);
    ss1 += __shfl_xor_sync(0xffffffffu, ss1, 2);
    float inv0 = 1.0f / fmaxf(sqrtf(ss0), 1e-12f);
    float inv1 = 1.0f / fmaxf(sqrtf(ss1), 1e-12f);

    int r0 = base + row0l + gr, r1 = base + row0l + gr + 8;
    if (w32) {
        float2* o2 = (float2*)(isU ? out_u : out_i);
        if (r0 < R) {
#pragma unroll
            for (int t = 0; t < 8; t++)
                o2[(size_t)r0 * 32 + t * 4 + tq] = make_float2(acc[t][0] * inv0, acc[t][1] * inv0);
        }
        if (r1 < R) {
#pragma unroll
            for (int t = 0; t < 8; t++)
                o2[(size_t)r1 * 32 + t * 4 + tq] = make_float2(acc[t][2] * inv1, acc[t][3] * inv1);
        }
    } else {
        __half2* out16 = isU ? o16_u : o16_i;
        if (r0 < R) {
#pragma unroll
            for (int t = 0; t < 8; t++)
                out16[(size_t)r0 * 32 + t * 4 + tq] =
                    __floats2half2_rn(acc[t][0] * inv0, acc[t][1] * inv0);
        }
        if (r1 < R) {
#pragma unroll
            for (int t = 0; t < 8; t++)
                out16[(size_t)r1 * 32 + t * 4 + tq] =
                    __floats2half2_rn(acc[t][2] * inv1, acc[t][3] * inv1);
        }
    }
}

// ---------------- launch ----------------
extern "C" void kernel_launch(void* const* d_in, const int* in_sizes, int n_in,
                              void* d_out, int out_size) {
    const float* user_emb = (const float*)d_in[0];
    const float* item_emb = (const float*)d_in[1];
    const float* Wu       = (const float*)d_in[2];   // [2,64,128]
    const float* Wi       = (const float*)d_in[3];
    const int*   u_idx    = (const int*)d_in[4];
    const int*   i_idx    = (const int*)d_in[5];
    const float* w_u2i    = (const float*)d_in[6];
    const float* w_i2u    = (const float*)d_in[7];
    float* out = (float*)d_out;

    void* p;
    int *u_cnt, *i_cnt;
    int2 *bkt_u, *bkt_i;
    __half2 *ue16, *ie16, *hu16, *hi16;
    cudaGetSymbolAddress(&p, g_u_cnt);  u_cnt  = (int*)p;
    cudaGetSymbolAddress(&p, g_i_cnt);  i_cnt  = (int*)p;
    cudaGetSymbolAddress(&p, g_bkt_u);  bkt_u  = (int2*)p;
    cudaGetSymbolAddress(&p, g_bkt_i);  bkt_i  = (int2*)p;
    cudaGetSymbolAddress(&p, g_ue16);   ue16   = (__half2*)p;
    cudaGetSymbolAddress(&p, g_ie16);   ie16   = (__half2*)p;
    cudaGetSymbolAddress(&p, g_hu16);   hu16   = (__half2*)p;
    cudaGetSymbolAddress(&p, g_hi16);   hi16   = (__half2*)p;

    static int attr_done = 0;
    if (!attr_done) {
        cudaFuncSetAttribute(fused_kernel, cudaFuncAttributeMaxDynamicSharedMemorySize, SMEMB);
        attr_done = 1;
    }

    // CSR build: init + scatter only
    init_kernel<<<1216, 256>>>(user_emb, item_emb, ue16, ie16, u_cnt, i_cnt);
    scatter_kernel<<<NE / 2 / 256, 256>>>(u_idx, i_idx, w_u2i, w_i2u,
                                          u_cnt, i_cnt, bkt_u, bkt_i);

    // layer 0: self/gather from fp16 input tables, write fp16 h tables only
    fused_kernel<<<UFB + IFB, 256, SMEMB>>>(ue16, ie16, ie16, ue16,
                                            u_cnt, i_cnt, bkt_u, bkt_i,
                                            Wu, Wi, (float*)0, (float*)0,
                                            hu16, hi16, 0);
    // layer 1: self/gather from fp16 h tables, write fp32 final outputs
    fused_kernel<<<UFB + IFB, 256, SMEMB>>>(hu16, hi16, hi16, hu16,
                                            u_cnt, i_cnt, bkt_u, bkt_i,
                                            Wu + 64 * 128, Wi + 64 * 128,
                                            out, out + (size_t)NU * DIM,
                                            (__half2*)0, (__half2*)0, 1);
}

// round 15
// speedup vs baseline: 1.2797x; 1.0126x over previous
#include <cuda_runtime.h>
#include <cuda_fp16.h>
#include <cstdint>

#define NU 200000
#define NI 100000
#define DIM 64
#define NE 3200000
#define CAPU 64          // max user degree (mean 16, sigma 4)
#define CAPI 128         // max item degree (mean 32, sigma 5.7)
#define UFB (NU / 64)    // 3125 fused blocks, u side
#define IFB ((NI + 63) / 64)  // 1563 (last block has 32 pad rows)

// ---------------- scratch (static __device__, no allocation) ----------------
__device__ int  g_u_cnt[NU];
__device__ int  g_i_cnt[NI];
__device__ __align__(16) int2 g_bkt_u[(size_t)NU * CAPU];   // (col, half2 weight)
__device__ __align__(16) int2 g_bkt_i[(size_t)NI * CAPI];
// fp16 tables (row = 32 half2 = 128B): inputs and layer-0 outputs
__device__ __align__(16) __half2 g_ue16[(size_t)NU * 32];
__device__ __align__(16) __half2 g_ie16[(size_t)NI * 32];
__device__ __align__(16) __half2 g_hu16[(size_t)NU * 32];
__device__ __align__(16) __half2 g_hi16[(size_t)NI * 32];

// ---------------- init: zero degree counters + fp16 table convert ----------------
__global__ void init_kernel(const float* __restrict__ ue, const float* __restrict__ ie,
                            __half2* __restrict__ ue16, __half2* __restrict__ ie16,
                            int* __restrict__ u_cnt, int* __restrict__ i_cnt) {
    int t = blockIdx.x * 256 + threadIdx.x;
    int N = gridDim.x * 256;
    for (int j = t; j < NU; j += N) u_cnt[j] = 0;
    for (int j = t; j < NI; j += N) i_cnt[j] = 0;
    const float2* ue2 = (const float2*)ue;
    for (int j = t; j < NU * 32; j += N) {
        float2 x = ue2[j];
        ue16[j] = __floats2half2_rn(x.x, x.y);
    }
    const float2* ie2 = (const float2*)ie;
    for (int j = t; j < NI * 32; j += N) {
        float2 x = ie2[j];
        ie16[j] = __floats2half2_rn(x.x, x.y);
    }
}

// ---------------- scatter: 4 edges/thread, weight pre-packed as half2 ----------------
__device__ __forceinline__ int packw(float w) {
    return (int)(__half_as_ushort(__float2half_rn(w)) * 0x10001u);
}

__global__ void scatter_kernel(const int* __restrict__ u_idx, const int* __restrict__ i_idx,
                               const float* __restrict__ w_u2i, const float* __restrict__ w_i2u,
                               int* __restrict__ u_cnt, int* __restrict__ i_cnt,
                               int2* __restrict__ bkt_u, int2* __restrict__ bkt_i) {
    int e = (blockIdx.x * 256 + threadIdx.x) * 4;
    if (e + 4 > NE) return;
    int4 u4 = *(const int4*)(u_idx + e);
    int4 i4 = *(const int4*)(i_idx + e);
    float4 wu = *(const float4*)(w_u2i + e);
    float4 wi = *(const float4*)(w_i2u + e);
    int pu0 = atomicAdd(&u_cnt[u4.x], 1);
    int pu1 = atomicAdd(&u_cnt[u4.y], 1);
    int pu2 = atomicAdd(&u_cnt[u4.z], 1);
    int pu3 = atomicAdd(&u_cnt[u4.w], 1);
    bkt_u[(size_t)u4.x * CAPU + pu0] = make_int2(i4.x, packw(wu.x));
    bkt_u[(size_t)u4.y * CAPU + pu1] = make_int2(i4.y, packw(wu.y));
    bkt_u[(size_t)u4.z * CAPU + pu2] = make_int2(i4.z, packw(wu.z));
    bkt_u[(size_t)u4.w * CAPU + pu3] = make_int2(i4.w, packw(wu.w));
    int pi0 = atomicAdd(&i_cnt[i4.x], 1);
    int pi1 = atomicAdd(&i_cnt[i4.y], 1);
    int pi2 = atomicAdd(&i_cnt[i4.z], 1);
    int pi3 = atomicAdd(&i_cnt[i4.w], 1);
    bkt_i[(size_t)i4.x * CAPI + pi0] = make_int2(u4.x, packw(wi.x));
    bkt_i[(size_t)i4.y * CAPI + pi1] = make_int2(u4.y, packw(wi.y));
    bkt_i[(size_t)i4.z * CAPI + pi2] = make_int2(u4.z, packw(wi.z));
    bkt_i[(size_t)i4.w * CAPI + pi3] = make_int2(u4.w, packw(wi.w));
}

// ---------------- fused layer: fp16 gather -> smem x -> mma gemm -> relu/L2 -> store ----------------
#define MMA16816(c, a0, a1, a2, a3, b0, b1)                                   \
    asm volatile("mma.sync.aligned.m16n8k16.row.col.f32.f16.f16.f32 "         \
                 "{%0,%1,%2,%3}, {%4,%5,%6,%7}, {%8,%9}, {%0,%1,%2,%3};"      \
                 : "+f"(c[0]), "+f"(c[1]), "+f"(c[2]), "+f"(c[3])             \
                 : "r"(a0), "r"(a1), "r"(a2), "r"(a3), "r"(b0), "r"(b1))

__device__ __forceinline__ __half2 shfl_xor_h2(__half2 v, int m) {
    unsigned u = *(unsigned*)&v;
    u = __shfl_xor_sync(0xffffffffu, u, m);
    return *(__half2*)&u;
}

// dynamic smem (halves): Whi[64*136], Wlo[64*136], Xhi[64*136] = 52224 B
#define SM_W  (64 * 136)
#define SMEMB (3 * SM_W * 2)

__global__ void __launch_bounds__(256, 4) fused_kernel(
    const __half2* __restrict__ self_u, const __half2* __restrict__ self_i,
    const __half2* __restrict__ tab_u,   // gather table for u rows (= item side)
    const __half2* __restrict__ tab_i,   // gather table for i rows (= user side)
    const int* __restrict__ cnt_u, const int* __restrict__ cnt_i,
    const int2* __restrict__ bkt_u, const int2* __restrict__ bkt_i,
    const float* __restrict__ Wu_l, const float* __restrict__ Wi_l,
    float* __restrict__ out_u, float* __restrict__ out_i,
    __half2* __restrict__ o16_u, __half2* __restrict__ o16_i,
    int w32)   // 1: write fp32 outputs (final layer); 0: write fp16 tables (layer 0)
{
    extern __shared__ __half sm[];
    __half* Whi = sm;
    __half* Wlo = sm + SM_W;
    __half* Xhi = sm + 2 * SM_W;
    __shared__ float pss[64][2];   // per-row partial sum of squares (2 n-halves)

    bool isU = blockIdx.x < UFB;
    int blk = isU ? blockIdx.x : blockIdx.x - UFB;
    int R = isU ? NU : NI;
    int base = blk * 64;
    const float* W = isU ? Wu_l : Wi_l;
    const __half2* hself = isU ? self_u : self_i;
    const float4* gt = (const float4*)(isU ? tab_u : tab_i);
    const int2* bkt = isU ? bkt_u : bkt_i;
    const int* cnt = isU ? cnt_u : cnt_i;
    int cap = isU ? CAPU : CAPI;

    // ---- fill W tiles (split fp16) ----
    for (int t = threadIdx.x; t < 64 * 128; t += 256) {
        int n = t >> 7, k = t & 127;
        float w = W[t];
        __half h = __float2half_rn(w);
        Whi[n * 136 + k] = h;
        Wlo[n * 136 + k] = __float2half_rn(w - __half2float(h));
    }

    int warp = threadIdx.x >> 5;
    int lane = threadIdx.x & 31;
    int q = lane >> 3;
    int m = lane & 7;

    // ---- gather phase: warp w handles rows base + w*8 .. +7 ----
#pragma unroll 1
    for (int r = 0; r < 8; r++) {
        int rloc = warp * 8 + r;
        int row = base + rloc;
        bool valid = row < R;
        int rowc = valid ? row : R - 1;
        int deg = valid ? cnt[rowc] : 0;
        int degm1 = deg - 1;
        int bb = rowc * cap;

        // self half: copy fp16 row directly into smem
        __half2 hs = hself[(size_t)rowc * 32 + lane];
        *(__half2*)&Xhi[rloc * 136 + 2 * lane] = hs;

        __half2 a0[4], a1[4];
#pragma unroll
        for (int j = 0; j < 4; j++) {
            a0[j] = __floats2half2_rn(0.f, 0.f);
            a1[j] = __floats2half2_rn(0.f, 0.f);
        }

        // clamped main loop: 8 edges/iter, 2 streams
        for (int e = 0; e < deg; e += 8) {
            int i0 = e + q, i1 = e + 4 + q;
            int2 E0 = __ldcs(bkt + bb + min(i0, degm1));
            int2 E1 = __ldcs(bkt + bb + min(i1, degm1));
            int wy0 = (i0 <= degm1) ? E0.y : 0;
            int wy1 = (i1 <= degm1) ? E1.y : 0;
            float4 r0 = gt[E0.x * 8 + m];
            float4 r1 = gt[E1.x * 8 + m];
            __half2 w0 = *(__half2*)&wy0;
            __half2 w1 = *(__half2*)&wy1;
            __half2* h0 = (__half2*)&r0;
            __half2* h1 = (__half2*)&r1;
#pragma unroll
            for (int j = 0; j < 4; j++) {
                a0[j] = __hfma2(h0[j], w0, a0[j]);
                a1[j] = __hfma2(h1[j], w1, a1[j]);
            }
        }

        // merge streams + reduce across the 4 lane-groups (packed fp16)
#pragma unroll
        for (int j = 0; j < 4; j++) {
            __half2 s = __hadd2(a0[j], a1[j]);
            s = __hadd2(s, shfl_xor_h2(s, 8));
            s = __hadd2(s, shfl_xor_h2(s, 16));
            a0[j] = s;
        }
        if (q == 0) {
#pragma unroll
            for (int j = 0; j < 4; j++)
                *(__half2*)&Xhi[rloc * 136 + 64 + m * 8 + 2 * j] = a0[j];
        }
    }
    __syncthreads();

    // ---- gemm phase: 8 warps; warp w = rows (w&3)*16, n-half (w>>2)*32 ----
    int gr = lane >> 2;      // 0..7
    int tq = lane & 3;       // 0..3
    int row0l = (warp & 3) * 16;
    int nhalf = warp >> 2;   // 0 or 1

    float acc[4][4];
#pragma unroll
    for (int t = 0; t < 4; t++)
#pragma unroll
        for (int j = 0; j < 4; j++) acc[t][j] = 0.f;

#pragma unroll
    for (int s = 0; s < 8; s++) {
        int ka = s * 16 + tq * 2;
        uint32_t ah0 = *(uint32_t*)&Xhi[(row0l + gr) * 136 + ka];
        uint32_t ah1 = *(uint32_t*)&Xhi[(row0l + gr + 8) * 136 + ka];
        uint32_t ah2 = *(uint32_t*)&Xhi[(row0l + gr) * 136 + ka + 8];
        uint32_t ah3 = *(uint32_t*)&Xhi[(row0l + gr + 8) * 136 + ka + 8];
#pragma unroll
        for (int t = 0; t < 4; t++) {
            int n = (nhalf * 4 + t) * 8 + gr;
            uint32_t bh0 = *(uint32_t*)&Whi[n * 136 + ka];
            uint32_t bh1 = *(uint32_t*)&Whi[n * 136 + ka + 8];
            uint32_t bl0 = *(uint32_t*)&Wlo[n * 136 + ka];
            uint32_t bl1 = *(uint32_t*)&Wlo[n * 136 + ka + 8];
            MMA16816(acc[t], ah0, ah1, ah2, ah3, bh0, bh1);   // Whi * x
            MMA16816(acc[t], ah0, ah1, ah2, ah3, bl0, bl1);   // Wlo * x
        }
    }

    // ---- epilogue: ReLU + partial row ssq -> smem -> L2 norm + store ----
    float ss0 = 0.f, ss1 = 0.f;
#pragma unroll
    for (int t = 0; t < 4; t++) {
        acc[t][0] = fmaxf(acc[t][0], 0.f);
        acc[t][1] = fmaxf(acc[t][1], 0.f);
        acc[t][2] = fmaxf(acc[t][2], 0.f);
        acc[t][3] = fmaxf(acc[t][3], 0.f);
        ss0 += acc[t][0] * acc[t][0] + acc[t][1] * acc[t][1];
        ss1 += acc[t][2] * acc[t][2] + acc[t][3] * acc[t][3];
    }
    ss0 += __shfl_xor_sync(0xffffffffu, ss0, 1);
    ss0 += __shfl_xor_sync(0xffffffffu, ss0, 2);
    ss1 += __shfl_xor_sync(0xffffffffu, ss1, 1);
    ss1 += __shfl_xor_sync(0xffffffffu, ss1, 2);
    if (tq == 0) {
        pss[row0l + gr][nhalf] = ss0;
        pss[row0l + gr + 8][nhalf] = ss1;
    }
    __syncthreads();
    float inv0 = rsqrtf(fmaxf(pss[row0l + gr][0] + pss[row0l + gr][1], 1e-24f));
    float inv1 = rsqrtf(fmaxf(pss[row0l + gr + 8][0] + pss[row0l + gr + 8][1], 1e-24f));

    int r0 = base + row0l + gr, r1 = base + row0l + gr + 8;
    int co = nhalf * 16;
    if (w32) {
        float2* o2 = (float2*)(isU ? out_u : out_i);
        if (r0 < R) {
#pragma unroll
            for (int t = 0; t < 4; t++)
                o2[(size_t)r0 * 32 + co + t * 4 + tq] = make_float2(acc[t][0] * inv0, acc[t][1] * inv0);
        }
        if (r1 < R) {
#pragma unroll
            for (int t = 0; t < 4; t++)
                o2[(size_t)r1 * 32 + co + t * 4 + tq] = make_float2(acc[t][2] * inv1, acc[t][3] * inv1);
        }
    } else {
        __half2* out16 = isU ? o16_u : o16_i;
        if (r0 < R) {
#pragma unroll
            for (int t = 0; t < 4; t++)
                out16[(size_t)r0 * 32 + co + t * 4 + tq] =
                    __floats2half2_rn(acc[t][0] * inv0, acc[t][1] * inv0);
        }
        if (r1 < R) {
#pragma unroll
            for (int t = 0; t < 4; t++)
                out16[(size_t)r1 * 32 + co + t * 4 + tq] =
                    __floats2half2_rn(acc[t][2] * inv1, acc[t][3] * inv1);
        }
    }
}

// ---------------- launch ----------------
extern "C" void kernel_launch(void* const* d_in, const int* in_sizes, int n_in,
                              void* d_out, int out_size) {
    const float* user_emb = (const float*)d_in[0];
    const float* item_emb = (const float*)d_in[1];
    const float* Wu       = (const float*)d_in[2];   // [2,64,128]
    const float* Wi       = (const float*)d_in[3];
    const int*   u_idx    = (const int*)d_in[4];
    const int*   i_idx    = (const int*)d_in[5];
    const float* w_u2i    = (const float*)d_in[6];
    const float* w_i2u    = (const float*)d_in[7];
    float* out = (float*)d_out;

    void* p;
    int *u_cnt, *i_cnt;
    int2 *bkt_u, *bkt_i;
    __half2 *ue16, *ie16, *hu16, *hi16;
    cudaGetSymbolAddress(&p, g_u_cnt);  u_cnt  = (int*)p;
    cudaGetSymbolAddress(&p, g_i_cnt);  i_cnt  = (int*)p;
    cudaGetSymbolAddress(&p, g_bkt_u);  bkt_u  = (int2*)p;
    cudaGetSymbolAddress(&p, g_bkt_i);  bkt_i  = (int2*)p;
    cudaGetSymbolAddress(&p, g_ue16);   ue16   = (__half2*)p;
    cudaGetSymbolAddress(&p, g_ie16);   ie16   = (__half2*)p;
    cudaGetSymbolAddress(&p, g_hu16);   hu16   = (__half2*)p;
    cudaGetSymbolAddress(&p, g_hi16);   hi16   = (__half2*)p;

    static int attr_done = 0;
    if (!attr_done) {
        cudaFuncSetAttribute(fused_kernel, cudaFuncAttributeMaxDynamicSharedMemorySize, SMEMB);
        attr_done = 1;
    }

    // CSR build: init + scatter only
    init_kernel<<<1216, 256>>>(user_emb, item_emb, ue16, ie16, u_cnt, i_cnt);
    scatter_kernel<<<NE / 4 / 256, 256>>>(u_idx, i_idx, w_u2i, w_i2u,
                                          u_cnt, i_cnt, bkt_u, bkt_i);

    // layer 0: self/gather from fp16 input tables, write fp16 h tables only
    fused_kernel<<<UFB + IFB, 256, SMEMB>>>(ue16, ie16, ie16, ue16,
                                            u_cnt, i_cnt, bkt_u, bkt_i,
                                            Wu, Wi, (float*)0, (float*)0,
                                            hu16, hi16, 0);
    // layer 1: self/gather from fp16 h tables, write fp32 final outputs
    fused_kernel<<<UFB + IFB, 256, SMEMB>>>(hu16, hi16, hi16, hu16,
                                            u_cnt, i_cnt, bkt_u, bkt_i,
                                            Wu + 64 * 128, Wi + 64 * 128,
                                            out, out + (size_t)NU * DIM,
                                            (__half2*)0, (__half2*)0, 1);
}

// round 16
// speedup vs baseline: 1.4260x; 1.1143x over previous
#include <cuda_runtime.h>
#include <cuda_fp16.h>
#include <cstdint>

#define NU 200000
#define NI 100000
#define DIM 64
#define NE 3200000
#define CAPU 64          // max user degree (mean 16, sigma 4)
#define CAPI 128         // max item degree (mean 32, sigma 5.7)
#define UFB (NU / 64)    // 3125 fused blocks, u side
#define IFB ((NI + 63) / 64)  // 1563 (last block has 32 pad rows)

// ---------------- scratch (static __device__, no allocation) ----------------
__device__ int  g_u_cnt[NU];
__device__ int  g_i_cnt[NI];
__device__ __align__(16) int2 g_bkt_u[(size_t)NU * CAPU];   // (col, half2 weight)
__device__ __align__(16) int2 g_bkt_i[(size_t)NI * CAPI];
// fp16 tables (row = 32 half2 = 128B): inputs and layer-0 outputs
__device__ __align__(16) __half2 g_ue16[(size_t)NU * 32];
__device__ __align__(16) __half2 g_ie16[(size_t)NI * 32];
__device__ __align__(16) __half2 g_hu16[(size_t)NU * 32];
__device__ __align__(16) __half2 g_hi16[(size_t)NI * 32];

// ---------------- init: zero degree counters + fp16 table convert ----------------
__global__ void init_kernel(const float* __restrict__ ue, const float* __restrict__ ie,
                            __half2* __restrict__ ue16, __half2* __restrict__ ie16,
                            int* __restrict__ u_cnt, int* __restrict__ i_cnt) {
    int t = blockIdx.x * 256 + threadIdx.x;
    int N = gridDim.x * 256;
    for (int j = t; j < NU; j += N) u_cnt[j] = 0;
    for (int j = t; j < NI; j += N) i_cnt[j] = 0;
    const float2* ue2 = (const float2*)ue;
    for (int j = t; j < NU * 32; j += N) {
        float2 x = ue2[j];
        ue16[j] = __floats2half2_rn(x.x, x.y);
    }
    const float2* ie2 = (const float2*)ie;
    for (int j = t; j < NI * 32; j += N) {
        float2 x = ie2[j];
        ie16[j] = __floats2half2_rn(x.x, x.y);
    }
}

// ---------------- scatter: 4 edges/thread, weight pre-packed as half2 ----------------
__device__ __forceinline__ int packw(float w) {
    return (int)(__half_as_ushort(__float2half_rn(w)) * 0x10001u);
}

__global__ void scatter_kernel(const int* __restrict__ u_idx, const int* __restrict__ i_idx,
                               const float* __restrict__ w_u2i, const float* __restrict__ w_i2u,
                               int* __restrict__ u_cnt, int* __restrict__ i_cnt,
                               int2* __restrict__ bkt_u, int2* __restrict__ bkt_i) {
    int e = (blockIdx.x * 256 + threadIdx.x) * 4;
    if (e + 4 > NE) return;
    int4 u4 = *(const int4*)(u_idx + e);
    int4 i4 = *(const int4*)(i_idx + e);
    float4 wu = *(const float4*)(w_u2i + e);
    float4 wi = *(const float4*)(w_i2u + e);
    int pu0 = atomicAdd(&u_cnt[u4.x], 1);
    int pu1 = atomicAdd(&u_cnt[u4.y], 1);
    int pu2 = atomicAdd(&u_cnt[u4.z], 1);
    int pu3 = atomicAdd(&u_cnt[u4.w], 1);
    bkt_u[(size_t)u4.x * CAPU + pu0] = make_int2(i4.x, packw(wu.x));
    bkt_u[(size_t)u4.y * CAPU + pu1] = make_int2(i4.y, packw(wu.y));
    bkt_u[(size_t)u4.z * CAPU + pu2] = make_int2(i4.z, packw(wu.z));
    bkt_u[(size_t)u4.w * CAPU + pu3] = make_int2(i4.w, packw(wu.w));
    int pi0 = atomicAdd(&i_cnt[i4.x], 1);
    int pi1 = atomicAdd(&i_cnt[i4.y], 1);
    int pi2 = atomicAdd(&i_cnt[i4.z], 1);
    int pi3 = atomicAdd(&i_cnt[i4.w], 1);
    bkt_i[(size_t)i4.x * CAPI + pi0] = make_int2(u4.x, packw(wi.x));
    bkt_i[(size_t)i4.y * CAPI + pi1] = make_int2(u4.y, packw(wi.y));
    bkt_i[(size_t)i4.z * CAPI + pi2] = make_int2(u4.z, packw(wi.z));
    bkt_i[(size_t)i4.w * CAPI + pi3] = make_int2(u4.w, packw(wi.w));
}

// ---------------- fused layer: fp16 gather -> smem x -> mma gemm -> relu/L2 -> store ----------------
#define MMA16816(c, a0, a1, a2, a3, b0, b1)                                   \
    asm volatile("mma.sync.aligned.m16n8k16.row.col.f32.f16.f16.f32 "         \
                 "{%0,%1,%2,%3}, {%4,%5,%6,%7}, {%8,%9}, {%0,%1,%2,%3};"      \
                 : "+f"(c[0]), "+f"(c[1]), "+f"(c[2]), "+f"(c[3])             \
                 : "r"(a0), "r"(a1), "r"(a2), "r"(a3), "r"(b0), "r"(b1))

__device__ __forceinline__ __half2 shfl_xor_h2(__half2 v, int m) {
    unsigned u = *(unsigned*)&v;
    u = __shfl_xor_sync(0xffffffffu, u, m);
    return *(__half2*)&u;
}

// dynamic smem (halves): Whi[64*136], Wlo[64*136], Xhi[64*136] = 52224 B
#define SM_W  (64 * 136)
#define SMEMB (3 * SM_W * 2)

__global__ void __launch_bounds__(256, 4) fused_kernel(
    const __half2* __restrict__ self_u, const __half2* __restrict__ self_i,
    const __half2* __restrict__ tab_u,   // gather table for u rows (= item side)
    const __half2* __restrict__ tab_i,   // gather table for i rows (= user side)
    const int* __restrict__ cnt_u, const int* __restrict__ cnt_i,
    const int2* __restrict__ bkt_u, const int2* __restrict__ bkt_i,
    const float* __restrict__ Wu_l, const float* __restrict__ Wi_l,
    float* __restrict__ out_u, float* __restrict__ out_i,
    __half2* __restrict__ o16_u, __half2* __restrict__ o16_i,
    int w32)   // 1: write fp32 outputs (final layer); 0: write fp16 tables (layer 0)
{
    extern __shared__ __half sm[];
    __half* Whi = sm;
    __half* Wlo = sm + SM_W;
    __half* Xhi = sm + 2 * SM_W;
    __shared__ float pss[64][2];   // per-row partial sum of squares (2 n-halves)

    bool isU = blockIdx.x < UFB;
    int blk = isU ? blockIdx.x : blockIdx.x - UFB;
    int R = isU ? NU : NI;
    int base = blk * 64;
    const float* W = isU ? Wu_l : Wi_l;
    const __half2* hself = isU ? self_u : self_i;
    const float4* gt = (const float4*)(isU ? tab_u : tab_i);
    const int2* bkt = isU ? bkt_u : bkt_i;
    const int* cnt = isU ? cnt_u : cnt_i;
    int cshift = isU ? 6 : 7;      // log2(CAPU/CAPI)

    // ---- fill W tiles (split fp16) ----
    for (int t = threadIdx.x; t < 64 * 128; t += 256) {
        int n = t >> 7, k = t & 127;
        float w = W[t];
        __half h = __float2half_rn(w);
        Whi[n * 136 + k] = h;
        Wlo[n * 136 + k] = __float2half_rn(w - __half2float(h));
    }

    int warp = threadIdx.x >> 5;
    int lane = threadIdx.x & 31;
    int q = lane >> 3;
    int m = lane & 7;

    // ---- gather phase: warp w handles rows base + w*8 .. +7 ----
#pragma unroll 1
    for (int r = 0; r < 8; r++) {
        int rloc = warp * 8 + r;
        int row = base + rloc;
        bool valid = row < R;
        int rowc = valid ? row : R - 1;
        int deg = valid ? cnt[rowc] : 0;
        int degm1 = deg - 1;
        int bb = rowc << cshift;

        // self half: copy fp16 row directly into smem
        __half2 hs = hself[(size_t)rowc * 32 + lane];
        *(__half2*)&Xhi[rloc * 136 + 2 * lane] = hs;

        __half2 a0[4], a1[4];
#pragma unroll
        for (int j = 0; j < 4; j++) {
            a0[j] = __floats2half2_rn(0.f, 0.f);
            a1[j] = __floats2half2_rn(0.f, 0.f);
        }

        // clamped main loop: 16 edges/iter, 4 load streams, 2 accumulator sets
        for (int e = 0; e < deg; e += 16) {
            int i0 = e + q, i1 = e + 4 + q, i2 = e + 8 + q, i3 = e + 12 + q;
            int2 E0 = __ldcs(bkt + bb + min(i0, degm1));
            int2 E1 = __ldcs(bkt + bb + min(i1, degm1));
            int2 E2 = __ldcs(bkt + bb + min(i2, degm1));
            int2 E3 = __ldcs(bkt + bb + min(i3, degm1));
            int wy0 = (i0 <= degm1) ? E0.y : 0;
            int wy1 = (i1 <= degm1) ? E1.y : 0;
            int wy2 = (i2 <= degm1) ? E2.y : 0;
            int wy3 = (i3 <= degm1) ? E3.y : 0;
            float4 r0 = gt[E0.x * 8 + m];
            float4 r1 = gt[E1.x * 8 + m];
            float4 r2 = gt[E2.x * 8 + m];
            float4 r3 = gt[E3.x * 8 + m];
            __half2 w0 = *(__half2*)&wy0;
            __half2 w1 = *(__half2*)&wy1;
            __half2 w2 = *(__half2*)&wy2;
            __half2 w3 = *(__half2*)&wy3;
            __half2* h0 = (__half2*)&r0;
            __half2* h1 = (__half2*)&r1;
            __half2* h2 = (__half2*)&r2;
            __half2* h3 = (__half2*)&r3;
#pragma unroll
            for (int j = 0; j < 4; j++) {
                a0[j] = __hfma2(h0[j], w0, a0[j]);
                a1[j] = __hfma2(h1[j], w1, a1[j]);
                a0[j] = __hfma2(h2[j], w2, a0[j]);
                a1[j] = __hfma2(h3[j], w3, a1[j]);
            }
        }

        // merge streams + reduce across the 4 lane-groups (packed fp16)
#pragma unroll
        for (int j = 0; j < 4; j++) {
            __half2 s = __hadd2(a0[j], a1[j]);
            s = __hadd2(s, shfl_xor_h2(s, 8));
            s = __hadd2(s, shfl_xor_h2(s, 16));
            a0[j] = s;
        }
        if (q == 0) {
#pragma unroll
            for (int j = 0; j < 4; j++)
                *(__half2*)&Xhi[rloc * 136 + 64 + m * 8 + 2 * j] = a0[j];
        }
    }
    __syncthreads();

    // ---- gemm phase: 8 warps; warp w = rows (w&3)*16, n-half (w>>2)*32 ----
    int gr = lane >> 2;      // 0..7
    int tq = lane & 3;       // 0..3
    int row0l = (warp & 3) * 16;
    int nhalf = warp >> 2;   // 0 or 1

    float acc[4][4];
#pragma unroll
    for (int t = 0; t < 4; t++)
#pragma unroll
        for (int j = 0; j < 4; j++) acc[t][j] = 0.f;

#pragma unroll
    for (int s = 0; s < 8; s++) {
        int ka = s * 16 + tq * 2;
        uint32_t ah0 = *(uint32_t*)&Xhi[(row0l + gr) * 136 + ka];
        uint32_t ah1 = *(uint32_t*)&Xhi[(row0l + gr + 8) * 136 + ka];
        uint32_t ah2 = *(uint32_t*)&Xhi[(row0l + gr) * 136 + ka + 8];
        uint32_t ah3 = *(uint32_t*)&Xhi[(row0l + gr + 8) * 136 + ka + 8];
#pragma unroll
        for (int t = 0; t < 4; t++) {
            int n = (nhalf * 4 + t) * 8 + gr;
            uint32_t bh0 = *(uint32_t*)&Whi[n * 136 + ka];
            uint32_t bh1 = *(uint32_t*)&Whi[n * 136 + ka + 8];
            uint32_t bl0 = *(uint32_t*)&Wlo[n * 136 + ka];
            uint32_t bl1 = *(uint32_t*)&Wlo[n * 136 + ka + 8];
            MMA16816(acc[t], ah0, ah1, ah2, ah3, bh0, bh1);   // Whi * x
            MMA16816(acc[t], ah0, ah1, ah2, ah3, bl0, bl1);   // Wlo * x
        }
    }

    // ---- epilogue: ReLU + partial row ssq -> smem -> L2 norm + store ----
    float ss0 = 0.f, ss1 = 0.f;
#pragma unroll
    for (int t = 0; t < 4; t++) {
        acc[t][0] = fmaxf(acc[t][0], 0.f);
        acc[t][1] = fmaxf(acc[t][1], 0.f);
        acc[t][2] = fmaxf(acc[t][2], 0.f);
        acc[t][3] = fmaxf(acc[t][3], 0.f);
        ss0 += acc[t][0] * acc[t][0] + acc[t][1] * acc[t][1];
        ss1 += acc[t][2] * acc[t][2] + acc[t][3] * acc[t][3];
    }
    ss0 += __shfl_xor_sync(0xffffffffu, ss0, 1);
    ss0 += __shfl_xor_sync(0xffffffffu, ss0, 2);
    ss1 += __shfl_xor_sync(0xffffffffu, ss1, 1);
    ss1 += __shfl_xor_sync(0xffffffffu, ss1, 2);
    if (tq == 0) {
        pss[row0l + gr][nhalf] = ss0;
        pss[row0l + gr + 8][nhalf] = ss1;
    }
    __syncthreads();
    float inv0 = rsqrtf(fmaxf(pss[row0l + gr][0] + pss[row0l + gr][1], 1e-24f));
    float inv1 = rsqrtf(fmaxf(pss[row0l + gr + 8][0] + pss[row0l + gr + 8][1], 1e-24f));

    int r0 = base + row0l + gr, r1 = base + row0l + gr + 8;
    int co = nhalf * 16;
    if (w32) {
        float2* o2 = (float2*)(isU ? out_u : out_i);
        if (r0 < R) {
#pragma unroll
            for (int t = 0; t < 4; t++)
                o2[(size_t)r0 * 32 + co + t * 4 + tq] = make_float2(acc[t][0] * inv0, acc[t][1] * inv0);
        }
        if (r1 < R) {
#pragma unroll
            for (int t = 0; t < 4; t++)
                o2[(size_t)r1 * 32 + co + t * 4 + tq] = make_float2(acc[t][2] * inv1, acc[t][3] * inv1);
        }
    } else {
        __half2* out16 = isU ? o16_u : o16_i;
        if (r0 < R) {
#pragma unroll
            for (int t = 0; t < 4; t++)
                out16[(size_t)r0 * 32 + co + t * 4 + tq] =
                    __floats2half2_rn(acc[t][0] * inv0, acc[t][1] * inv0);
        }
        if (r1 < R) {
#pragma unroll
            for (int t = 0; t < 4; t++)
                out16[(size_t)r1 * 32 + co + t * 4 + tq] =
                    __floats2half2_rn(acc[t][2] * inv1, acc[t][3] * inv1);
        }
    }
}

// ---------------- launch ----------------
extern "C" void kernel_launch(void* const* d_in, const int* in_sizes, int n_in,
                              void* d_out, int out_size) {
    const float* user_emb = (const float*)d_in[0];
    const float* item_emb = (const float*)d_in[1];
    const float* Wu       = (const float*)d_in[2];   // [2,64,128]
    const float* Wi       = (const float*)d_in[3];
    const int*   u_idx    = (const int*)d_in[4];
    const int*   i_idx    = (const int*)d_in[5];
    const float* w_u2i    = (const float*)d_in[6];
    const float* w_i2u    = (const float*)d_in[7];
    float* out = (float*)d_out;

    void* p;
    int *u_cnt, *i_cnt;
    int2 *bkt_u, *bkt_i;
    __half2 *ue16, *ie16, *hu16, *hi16;
    cudaGetSymbolAddress(&p, g_u_cnt);  u_cnt  = (int*)p;
    cudaGetSymbolAddress(&p, g_i_cnt);  i_cnt  = (int*)p;
    cudaGetSymbolAddress(&p, g_bkt_u);  bkt_u  = (int2*)p;
    cudaGetSymbolAddress(&p, g_bkt_i);  bkt_i  = (int2*)p;
    cudaGetSymbolAddress(&p, g_ue16);   ue16   = (__half2*)p;
    cudaGetSymbolAddress(&p, g_ie16);   ie16   = (__half2*)p;
    cudaGetSymbolAddress(&p, g_hu16);   hu16   = (__half2*)p;
    cudaGetSymbolAddress(&p, g_hi16);   hi16   = (__half2*)p;

    static int attr_done = 0;
    if (!attr_done) {
        cudaFuncSetAttribute(fused_kernel, cudaFuncAttributeMaxDynamicSharedMemorySize, SMEMB);
        attr_done = 1;
    }

    // CSR build: init + scatter only
    init_kernel<<<1216, 256>>>(user_emb, item_emb, ue16, ie16, u_cnt, i_cnt);
    scatter_kernel<<<NE / 4 / 256, 256>>>(u_idx, i_idx, w_u2i, w_i2u,
                                          u_cnt, i_cnt, bkt_u, bkt_i);

    // layer 0: self/gather from fp16 input tables, write fp16 h tables only
    fused_kernel<<<UFB + IFB, 256, SMEMB>>>(ue16, ie16, ie16, ue16,
                                            u_cnt, i_cnt, bkt_u, bkt_i,
                                            Wu, Wi, (float*)0, (float*)0,
                                            hu16, hi16, 0);
    // layer 1: self/gather from fp16 h tables, write fp32 final outputs
    fused_kernel<<<UFB + IFB, 256, SMEMB>>>(hu16, hi16, hi16, hu16,
                                            u_cnt, i_cnt, bkt_u, bkt_i,
                                            Wu + 64 * 128, Wi + 64 * 128,
                                            out, out + (size_t)NU * DIM,
                                            (__half2*)0, (__half2*)0, 1);
}